// round 16
// baseline (speedup 1.0000x reference)
#include <cuda_runtime.h>
#include <cuda_bf16.h>

// ShiftImgPreprocessor: out[b,t,c,i,j] = img[b,t,c, clamp(i+sy-PAD,0,H-1),
//                                              clamp(j+sx-PAD,0,W-1)] / 255 - 0.5
// img (256,4,3,96,96) fp32, shift (256,2) int32 (sx=shift[b][0], sy=shift[b][1]).
//
// R14: persistent grid-stride kernel. R13 showed achieved occ stuck ~61%
// despite no resource limit -> block churn (9216 x ~0.5us CTAs) leaves warp
// slots idle between CTAs. Launch ~full-residency blocks (148 SMs x 6 CTAs)
// that loop over row-groups; warps stay resident the whole kernel and keep
// 24-deep front-batched load bundles continuously in flight. Inner work is
// identical to R5/R13 (8 rows/warp, warp-contiguous, aligned STG.32).

#define PAD 4
#define N_IMG 256
#define T_IMG 4
#define C_IMG 3
#define H_IMG 96
#define W_IMG 96
#define TC (T_IMG * C_IMG)                    // 12 planes per batch
#define N_PLANES (N_IMG * TC)                 // 3072
#define ROWS_PER_WARP 8
#define WARPS_PER_BLOCK 8
#define THREADS (WARPS_PER_BLOCK * 32)        // 256
#define ROWS_PER_GROUP (WARPS_PER_BLOCK * ROWS_PER_WARP)   // 64
#define TOTAL_ROWS (N_PLANES * H_IMG)         // 294912
#define NGROUPS (TOTAL_ROWS / ROWS_PER_GROUP) // 4608
#define NSM 148
#define CTAS_PER_SM 6
#define NBLOCKS (NSM * CTAS_PER_SM)           // 888

__global__ __launch_bounds__(THREADS) void shift_img_kernel(
    const float* __restrict__ img,
    const int*   __restrict__ shift,
    float*       __restrict__ out)
{
    const int warp = threadIdx.x >> 5;
    const int lane = threadIdx.x & 31;
    const float INV255 = 1.0f / 255.0f;

    for (int g = blockIdx.x; g < NGROUPS; g += NBLOCKS) {
        const int base = g * ROWS_PER_GROUP + warp * ROWS_PER_WARP; // first row

        const int plane = base / H_IMG;      // flattened (b,t,c); same for all 8 rows
        const int i0    = base % H_IMG;
        const int b     = plane / TC;

        const int sx = __ldg(&shift[2 * b + 0]);
        const int sy = __ldg(&shift[2 * b + 1]);
        const int d  = sx - PAD;             // in [-4, 4]

        const int x0 = min(max(lane +  0 + d, 0), W_IMG - 1);
        const int x1 = min(max(lane + 32 + d, 0), W_IMG - 1);
        const int x2 = min(max(lane + 64 + d, 0), W_IMG - 1);

        const float* sp = img + (size_t)plane * (H_IMG * W_IMG);
        float*       dp = out + (size_t)base  * W_IMG;

        // ---- front-batch all 24 independent loads (deep MLP) ----
        float v[ROWS_PER_WARP][3];
        #pragma unroll
        for (int k = 0; k < ROWS_PER_WARP; k++) {
            const int sY = min(max(i0 + k + sy - PAD, 0), H_IMG - 1);
            const float* r = sp + sY * W_IMG;
            v[k][0] = __ldg(r + x0);
            v[k][1] = __ldg(r + x1);
            v[k][2] = __ldg(r + x2);
        }

        // ---- normalize + aligned contiguous stores ----
        #pragma unroll
        for (int k = 0; k < ROWS_PER_WARP; k++) {
            float* w = dp + k * W_IMG;
            w[lane +  0] = fmaf(v[k][0], INV255, -0.5f);
            w[lane + 32] = fmaf(v[k][1], INV255, -0.5f);
            w[lane + 64] = fmaf(v[k][2], INV255, -0.5f);
        }
    }
}

extern "C" void kernel_launch(void* const* d_in, const int* in_sizes, int n_in,
                              void* d_out, int out_size)
{
    const float* img   = (const float*)d_in[0];
    const int*   shift = (const int*)d_in[1];
    float*       out   = (float*)d_out;

    shift_img_kernel<<<NBLOCKS, THREADS>>>(img, shift, out);
}

// round 17
// speedup vs baseline: 1.0800x; 1.0800x over previous
#include <cuda_runtime.h>
#include <cuda_bf16.h>

// ShiftImgPreprocessor: out[b,t,c,i,j] = img[b,t,c, clamp(i+sy-PAD,0,H-1),
//                                              clamp(j+sx-PAD,0,W-1)] / 255 - 0.5
// img (256,4,3,96,96) fp32, shift (256,2) int32 (sx=shift[b][0], sy=shift[b][1]).
//
// R16: fully vectorized with register realignment. Warp loads its 4 contiguous
// source rows as ALIGNED float4 (3 LDG.128/lane), shifts the whole 384-float
// block by d floats using one shuffled neighbor slot per output slot (|d|<=4
// -> exactly one neighbor needed), patches the <=4 clamped edge columns per
// row from its own registers, stores aligned STG.128. 4x fewer memory
// instructions / ~2-3x fewer L1 wavefronts than the scalar variants. Warp-
// uniform scalar fallback for row-groups whose Y-window clamps at plane edges.

#define PAD 4
#define N_IMG 256
#define T_IMG 4
#define C_IMG 3
#define H_IMG 96
#define W_IMG 96
#define TC (T_IMG * C_IMG)                    // 12 planes per batch
#define N_PLANES (N_IMG * TC)                 // 3072
#define ROWS_PER_WARP 4
#define WARPS_PER_BLOCK 8
#define THREADS (WARPS_PER_BLOCK * 32)        // 256
#define ROWS_PER_BLOCK (WARPS_PER_BLOCK * ROWS_PER_WARP)   // 32
#define TOTAL_ROWS (N_PLANES * H_IMG)         // 294912
#define NBLOCKS (TOTAL_ROWS / ROWS_PER_BLOCK) // 9216
#define W4 (W_IMG / 4)                        // 24 float4 per row

__device__ __forceinline__ float4 shfl_f4(float4 v, int src) {
    float4 r;
    r.x = __shfl_sync(0xffffffffu, v.x, src);
    r.y = __shfl_sync(0xffffffffu, v.y, src);
    r.z = __shfl_sync(0xffffffffu, v.z, src);
    r.w = __shfl_sync(0xffffffffu, v.w, src);
    return r;
}

// out[t] = (t+dr < 4) ? A[t+dr] : B[t+dr-4],  dr in [0,3] (warp-uniform)
__device__ __forceinline__ float4 funnel(float4 A, float4 B, int dr) {
    switch (dr) {
        case 0:  return A;
        case 1:  return make_float4(A.y, A.z, A.w, B.x);
        case 2:  return make_float4(A.z, A.w, B.x, B.y);
        default: return make_float4(A.w, B.x, B.y, B.z);
    }
}

__device__ __forceinline__ float4 norm4(float4 v) {
    const float INV255 = 1.0f / 255.0f;
    v.x = fmaf(v.x, INV255, -0.5f);
    v.y = fmaf(v.y, INV255, -0.5f);
    v.z = fmaf(v.z, INV255, -0.5f);
    v.w = fmaf(v.w, INV255, -0.5f);
    return v;
}

__global__ __launch_bounds__(THREADS) void shift_img_kernel(
    const float* __restrict__ img,
    const int*   __restrict__ shift,
    float*       __restrict__ out)
{
    const int warp = threadIdx.x >> 5;
    const int lane = threadIdx.x & 31;
    const int base = blockIdx.x * ROWS_PER_BLOCK + warp * ROWS_PER_WARP;

    const int plane = base / H_IMG;
    const int i0    = base % H_IMG;
    const int b     = plane / TC;

    const int sx = __ldg(&shift[2 * b + 0]);
    const int sy = __ldg(&shift[2 * b + 1]);
    const int d  = sx - PAD;                  // in [-4, 4]

    const float* sp = img + (size_t)plane * (H_IMG * W_IMG);
    const int sY0 = i0 + sy - PAD;
    const bool fast = (sY0 >= 0) && (sY0 + ROWS_PER_WARP - 1 < H_IMG);

    if (fast) {
        // ---- aligned vector loads of the contiguous 4-row source block ----
        const float4* s4 = reinterpret_cast<const float4*>(sp + sY0 * W_IMG);
        float4 bb[3];
        bb[0] = __ldg(s4 + lane);
        bb[1] = __ldg(s4 + lane + 32);
        bb[2] = __ldg(s4 + lane + 64);

        float4* d4 = reinterpret_cast<float4*>(out) + (size_t)base * W4;

        if (d == 0) {
            d4[lane +  0] = norm4(bb[0]);
            d4[lane + 32] = norm4(bb[1]);
            d4[lane + 64] = norm4(bb[2]);
        } else if (d > 0) {
            const int dr = d & 3;             // d=4 -> 0
            #pragma unroll
            for (int j = 0; j < 3; j++) {
                float4 bj  = bb[j];
                float4 bj1 = bb[j < 2 ? j + 1 : 2];   // j=2 neighbor is garbage, always patched/unused
                // neighbor slot S(m+1): contributor lane 0 supplies its next reg
                float4 var = (lane == 0) ? bj1 : bj;
                float4 nb  = shfl_f4(var, (lane + 1) & 31);
                float4 A   = (d == 4) ? nb : bj;
                float4 o   = funnel(A, nb, dr);
                // edge patch: last float4 of each row replicates col 95
                if (((lane + 32 * j) % W4) == W4 - 1) {
                    float e = bj.w;
                    o.w = e;
                    if (d >= 2) o.z = e;
                    if (d >= 3) o.y = e;
                    if (d >= 4) o.x = e;
                }
                d4[lane + 32 * j] = norm4(o);
            }
        } else {                               // d < 0
            const int dn = -d;                 // 1..4
            const int dr = (d + 4) & 3;        // -4 -> 0
            #pragma unroll
            for (int j = 0; j < 3; j++) {
                float4 bj  = bb[j];
                float4 bjm = bb[j > 0 ? j - 1 : 0];   // j=0 neighbor garbage, always patched/unused
                // neighbor slot S(m-1): contributor lane 31 supplies its previous reg
                float4 var = (lane == 31) ? bjm : bj;
                float4 nb  = shfl_f4(var, (lane + 31) & 31);
                float4 o   = funnel(nb, bj, dr);
                // edge patch: first float4 of each row replicates col 0
                if (((lane + 32 * j) % W4) == 0) {
                    float e = bj.x;
                    o.x = e;
                    if (dn >= 2) o.y = e;
                    if (dn >= 3) o.z = e;
                    if (dn >= 4) o.w = e;
                }
                d4[lane + 32 * j] = norm4(o);
            }
        }
    } else {
        // ---- scalar fallback for Y-clamped groups (plane top/bottom) ----
        const float INV255 = 1.0f / 255.0f;
        const int x0 = min(max(lane +  0 + d, 0), W_IMG - 1);
        const int x1 = min(max(lane + 32 + d, 0), W_IMG - 1);
        const int x2 = min(max(lane + 64 + d, 0), W_IMG - 1);
        float* dp = out + (size_t)base * W_IMG;

        float v[ROWS_PER_WARP][3];
        #pragma unroll
        for (int k = 0; k < ROWS_PER_WARP; k++) {
            const int sY = min(max(i0 + k + sy - PAD, 0), H_IMG - 1);
            const float* r = sp + sY * W_IMG;
            v[k][0] = __ldg(r + x0);
            v[k][1] = __ldg(r + x1);
            v[k][2] = __ldg(r + x2);
        }
        #pragma unroll
        for (int k = 0; k < ROWS_PER_WARP; k++) {
            float* w = dp + k * W_IMG;
            w[lane +  0] = fmaf(v[k][0], INV255, -0.5f);
            w[lane + 32] = fmaf(v[k][1], INV255, -0.5f);
            w[lane + 64] = fmaf(v[k][2], INV255, -0.5f);
        }
    }
}

extern "C" void kernel_launch(void* const* d_in, const int* in_sizes, int n_in,
                              void* d_out, int out_size)
{
    const float* img   = (const float*)d_in[0];
    const int*   shift = (const int*)d_in[1];
    float*       out   = (float*)d_out;

    shift_img_kernel<<<NBLOCKS, THREADS>>>(img, shift, out);
}